// round 6
// baseline (speedup 1.0000x reference)
#include <cuda_runtime.h>

#define N_ITEMS  262144
#define DIM      128
#define NCB      3
#define KCW      256
#define MT       64
#define NTHREADS 512
#define RS2      130   // packed-row stride in 8-byte units (1040B)

#define FMA2(d, a, b) asm("fma.rn.f32x2 %0, %1, %2, %0;" : "+l"(d) : "l"(a), "l"(b))

__device__ float g_cc[NCB * KCW];

__global__ void cc_kernel(const float* __restrict__ codebooks) {
    int stage = blockIdx.x;
    int j = threadIdx.x;
    const float* row = codebooks + ((size_t)stage * KCW + j) * DIM;
    double s = 0.0;
    #pragma unroll 8
    for (int k = 0; k < DIM; k++) { double v = (double)row[k]; s += v * v; }
    g_cc[stage * KCW + j] = (float)s;
}

// smem layout (bytes)
#define OFF_CBP   0                         // 128 pair-rows * RS2*8 = 133120
#define OFF_RRES  133120                    // 64 rows * RS2*8       =  66560
#define OFF_RRD   199680                    // 256 doubles           =   2048
#define OFF_REDV  201728                    // 32*64 float           =   8192
#define OFF_REDI  209920                    // 32*64 int             =   8192
#define OFF_CCS   218112                    // 256 float             =   1024
#define OFF_RRS   219136                    // 64 float              =    256
#define OFF_BEST  219392                    // 3*64 int              =    768
#define SMEM_BYTES 220160

__global__ __launch_bounds__(NTHREADS, 1)
void rvq_kernel(const float* __restrict__ x,
                const float* __restrict__ codebooks,
                float* __restrict__ out, int mode)
{
    extern __shared__ char smem[];
    unsigned long long* cbp   = (unsigned long long*)(smem + OFF_CBP);
    unsigned long long* rres2 = (unsigned long long*)(smem + OFF_RRES);
    double* rrd  = (double*)(smem + OFF_RRD);
    float*  redv = (float*)(smem + OFF_REDV);
    int*    redi = (int*)(smem + OFF_REDI);
    float*  cc_s = (float*)(smem + OFF_CCS);
    float*  rrs  = (float*)(smem + OFF_RRS);
    int*    best = (int*)(smem + OFF_BEST);

    const int t    = threadIdx.x;
    const int w    = t >> 5;
    const int lane = t & 31;
    // warp-structured mapping: R loads 8 distinct addrs/warp, C loads 4 distinct
    const int itemgrp = (lane & 7) | ((w & 1) << 3);   // items itemgrp + 16u, u<4
    const int cg      = (lane >> 3) | ((w >> 1) << 2); // pairs  cg + 32*v2,  v2<4
    const int itemBase = blockIdx.x * MT;

    // ---- init rres2 = (x, x) doubled pairs ----
    {
        const float4* xg = (const float4*)(x + (size_t)itemBase * DIM);
        #pragma unroll
        for (int n = 0; n < 4; n++) {
            int idx = t + NTHREADS * n;      // 0..2047
            int row = idx >> 5;
            int c4  = idx & 31;
            float4 v = xg[idx];
            float2* d = (float2*)&rres2[row * RS2 + c4 * 4];
            d[0] = make_float2(v.x, v.x);
            d[1] = make_float2(v.y, v.y);
            d[2] = make_float2(v.z, v.z);
            d[3] = make_float2(v.w, v.w);
        }
    }

    for (int stage = 0; stage < NCB; stage++) {
        __syncthreads();
        // ---- build packed codebook: cbp[p][k] = (c_{2p}[k], c_{2p+1}[k]) ----
        {
            const float4* cgm = (const float4*)(codebooks + (size_t)stage * KCW * DIM);
            #pragma unroll
            for (int n = 0; n < 8; n++) {
                int idx = t + NTHREADS * n;  // 0..4095
                int p  = idx >> 5;
                int c4 = idx & 31;
                float4 a = cgm[(2 * p)     * (DIM / 4) + c4];
                float4 b = cgm[(2 * p + 1) * (DIM / 4) + c4];
                float2* d = (float2*)&cbp[p * RS2 + c4 * 4];
                d[0] = make_float2(a.x, b.x);
                d[1] = make_float2(a.y, b.y);
                d[2] = make_float2(a.z, b.z);
                d[3] = make_float2(a.w, b.w);
            }
            if (t < KCW) cc_s[t] = g_cc[stage * KCW + t];
        }
        // ---- rrs partials: 4 threads/item, 32-deep double chains (R5-exact) ----
        if (t < 4 * MT) {
            int item = t >> 2, part = t & 3;
            const float2* rp = (const float2*)&rres2[item * RS2];
            double s = 0.0;
            #pragma unroll 8
            for (int k = part * 32; k < part * 32 + 32; k++) {
                double v = (double)rp[k].x; s += v * v;
            }
            rrd[t] = s;
        }
        __syncthreads();
        if (t < MT) {
            double s = ((rrd[4 * t] + rrd[4 * t + 1]) + rrd[4 * t + 2]) + rrd[4 * t + 3];
            rrs[t] = (float)s;
        }

        // ---- dot tile: acc2[u][v2], each f32x2 lane a sequential k-chain ----
        unsigned long long acc2[4][4];
        #pragma unroll
        for (int u = 0; u < 4; u++)
            #pragma unroll
            for (int v2 = 0; v2 < 4; v2++) acc2[u][v2] = 0ULL;

        const unsigned long long* rbase = &rres2[itemgrp * RS2];
        const unsigned long long* cbase = &cbp[cg * RS2];

        ulonglong2 Ar[4], Ac[4], Br[4], Bc[4];

        auto LOADH = [&](ulonglong2* R, ulonglong2* C, int h) {
            #pragma unroll
            for (int u = 0; u < 4; u++)
                R[u] = *(const ulonglong2*)&rbase[u * 16 * RS2 + 2 * h];
            #pragma unroll
            for (int v2 = 0; v2 < 4; v2++)
                C[v2] = *(const ulonglong2*)&cbase[v2 * 32 * RS2 + 2 * h];
        };
        auto FMAH = [&](const ulonglong2* R, const ulonglong2* C) {
            #pragma unroll
            for (int u = 0; u < 4; u++)
                #pragma unroll
                for (int v2 = 0; v2 < 4; v2++)
                    FMA2(acc2[u][v2], R[u].x, C[v2].x);   // k = 2h
            #pragma unroll
            for (int u = 0; u < 4; u++)
                #pragma unroll
                for (int v2 = 0; v2 < 4; v2++)
                    FMA2(acc2[u][v2], R[u].y, C[v2].y);   // k = 2h+1
        };

        LOADH(Ar, Ac, 0);
        #pragma unroll 1
        for (int h = 0; h < DIM / 2 - 2; h += 2) {
            LOADH(Br, Bc, h + 1);
            FMAH(Ar, Ac);
            LOADH(Ar, Ac, h + 2);
            FMAH(Br, Bc);
        }
        LOADH(Br, Bc, DIM / 2 - 1);
        FMAH(Ar, Ac);
        FMAH(Br, Bc);

        __syncthreads();   // rrs ready

        // ---- argmin of d2 = fl(fl(rr - 2*dot) + cc), cw ascending per thread ----
        #pragma unroll
        for (int u = 0; u < 4; u++) {
            int item = itemgrp + 16 * u;
            float rrv = rrs[item];
            float bv = 3.0e38f; int bi = KCW;
            #pragma unroll
            for (int v2 = 0; v2 < 4; v2++) {
                float2 dp = *(float2*)&acc2[u][v2];
                int cw = 2 * (cg + 32 * v2);
                float d2a = __fadd_rn(__fmaf_rn(-2.0f, dp.x, rrv), cc_s[cw]);
                if (d2a < bv) { bv = d2a; bi = cw; }
                float d2b = __fadd_rn(__fmaf_rn(-2.0f, dp.y, rrv), cc_s[cw + 1]);
                if (d2b < bv) { bv = d2b; bi = cw + 1; }
            }
            redv[cg * MT + item] = bv;
            redi[cg * MT + item] = bi;
        }
        __syncthreads();

        // ---- reduce 32 slots per item; tie-break: smaller index ----
        if (t < MT) {
            float bv = 3.0e38f; int bi = KCW;
            #pragma unroll 4
            for (int s2 = 0; s2 < 32; s2++) {
                float v  = redv[s2 * MT + t];
                int   i2 = redi[s2 * MT + t];
                if (v < bv || (v == bv && i2 < bi)) { bv = v; bi = i2; }
            }
            best[stage * MT + t] = bi;
            size_t gi = (size_t)(itemBase + t);
            if (mode == 0)      out[gi * 3 + stage] = (float)bi;
            else if (mode == 2) ((int*)out)[gi * 3 + stage] = bi;
        }
        __syncthreads();

        // ---- residual -= chosen codeword (doubled store) ----
        if (stage < NCB - 1) {
            #pragma unroll
            for (int n = 0; n < 8; n++) {
                int e    = t + NTHREADS * n;   // 0..4095
                int item = e >> 6;
                int k2   = e & 63;
                int bi   = best[stage * MT + item];
                const float2* cp = (const float2*)&cbp[(bi >> 1) * RS2 + 2 * k2];
                float2 c0 = cp[0], c1 = cp[1];
                float ca  = (bi & 1) ? c0.y : c0.x;
                float cb2 = (bi & 1) ? c1.y : c1.x;
                float2* rp = (float2*)&rres2[item * RS2 + 2 * k2];
                float r0 = rp[0].x, r1 = rp[1].x;
                float n0 = __fsub_rn(r0, ca);
                float n1 = __fsub_rn(r1, cb2);
                rp[0] = make_float2(n0, n0);
                rp[1] = make_float2(n1, n1);
            }
        }
    }
    __syncthreads();

    // ---- quantized = (c0[i0] + c1[i1]) + c2[i2], reference order ----
    if (mode != 2) {
        float* outq = (mode == 0) ? (out + (size_t)N_ITEMS * 3) : out;
        float4* oq4 = (float4*)outq;
        const float4* cb4 = (const float4*)codebooks;
        #pragma unroll
        for (int n = 0; n < 4; n++) {
            int e    = t + NTHREADS * n;   // 0..2047
            int item = e >> 5;
            int c4   = e & 31;
            int i0 = best[0 * MT + item];
            int i1 = best[1 * MT + item];
            int i2 = best[2 * MT + item];
            float4 q0 = cb4[(size_t)(0 * KCW + i0) * (DIM / 4) + c4];
            float4 q1 = cb4[(size_t)(1 * KCW + i1) * (DIM / 4) + c4];
            float4 q2 = cb4[(size_t)(2 * KCW + i2) * (DIM / 4) + c4];
            float4 q;
            q.x = __fadd_rn(__fadd_rn(q0.x, q1.x), q2.x);
            q.y = __fadd_rn(__fadd_rn(q0.y, q1.y), q2.y);
            q.z = __fadd_rn(__fadd_rn(q0.z, q1.z), q2.z);
            q.w = __fadd_rn(__fadd_rn(q0.w, q1.w), q2.w);
            oq4[(size_t)itemBase * (DIM / 4) + e] = q;
        }
    }
}

extern "C" void kernel_launch(void* const* d_in, const int* in_sizes, int n_in,
                              void* d_out, int out_size)
{
    const float* x   = (const float*)d_in[0];
    const float* cbk = (const float*)d_in[1];
    if (n_in >= 2 && in_sizes[0] == NCB * KCW * DIM && in_sizes[1] == N_ITEMS * DIM) {
        const float* tmp = x; x = cbk; cbk = tmp;
    }

    int mode;
    if (out_size == N_ITEMS * (3 + DIM))      mode = 0;
    else if (out_size == N_ITEMS * DIM)       mode = 1;
    else if (out_size == N_ITEMS * 3)         mode = 2;
    else                                       mode = (out_size > N_ITEMS * DIM) ? 0 : 1;

    cc_kernel<<<NCB, KCW>>>(cbk);
    cudaFuncSetAttribute(rvq_kernel, cudaFuncAttributeMaxDynamicSharedMemorySize, SMEM_BYTES);
    rvq_kernel<<<N_ITEMS / MT, NTHREADS, SMEM_BYTES>>>(x, cbk, (float*)d_out, mode);
}

// round 7
// speedup vs baseline: 1.0305x; 1.0305x over previous
#include <cuda_runtime.h>
#include <cstdint>

#define N_ITEMS  262144
#define DIM      128
#define NCB      3
#define KCW      256
#define MT       64
#define NTHREADS 512
#define GRID     152
#define NTILES   (N_ITEMS / MT)      // 4096
#define RSP      132                 // plain residual row stride (floats)
#define RS2      130                 // packed codebook row stride (ulonglong)
#define CBPN     (128 * RS2)         // 16640 ull per stage

#define FMA2(d, a, b) asm("fma.rn.f32x2 %0, %1, %2, %0;" : "+l"(d) : "l"(a), "l"(b))

__device__ __forceinline__ unsigned long long dup2(float f) {
    unsigned long long d; unsigned u = __float_as_uint(f);
    asm("mov.b64 %0, {%1, %1};" : "=l"(d) : "r"(u));
    return d;
}
__device__ __forceinline__ uint32_t s2u(const void* p) {
    return (uint32_t)__cvta_generic_to_shared(p);
}
#define CPA16(saddr, gptr) asm volatile("cp.async.ca.shared.global [%0], [%1], 16;" :: "r"(saddr), "l"(gptr))
#define CPCOMMIT()         asm volatile("cp.async.commit_group;")
#define CPWAIT0()          asm volatile("cp.async.wait_group 0;" ::: "memory")

__device__ float              g_cc[NCB * KCW];
__device__ unsigned long long g_cbp[NCB * CBPN];
__device__ float              g_res[(size_t)N_ITEMS * DIM];
__device__ int                g_idx[2 * N_ITEMS];

// ---- ||c||^2 in double (sequential k chain, as validated in R3-R6) ----
__global__ void cc_kernel(const float* __restrict__ codebooks) {
    int stage = blockIdx.x, j = threadIdx.x;
    const float* row = codebooks + ((size_t)stage * KCW + j) * DIM;
    double s = 0.0;
    #pragma unroll 8
    for (int k = 0; k < DIM; k++) { double v = (double)row[k]; s += v * v; }
    g_cc[stage * KCW + j] = (float)s;
}

// ---- prepack codebooks: g_cbp[s][p*RS2+k] = (c_{2p}[k], c_{2p+1}[k]) ----
__global__ void prepack_kernel(const float* __restrict__ codebooks) {
    int idx = blockIdx.x * blockDim.x + threadIdx.x;   // 0..49151
    if (idx >= NCB * 128 * DIM) return;
    int s = idx / (128 * DIM);
    int r = idx % (128 * DIM);
    int p = r / DIM, k = r % DIM;
    float a = codebooks[((size_t)s * KCW + 2 * p)     * DIM + k];
    float b = codebooks[((size_t)s * KCW + 2 * p + 1) * DIM + k];
    *(float2*)&g_cbp[s * CBPN + p * RS2 + k] = make_float2(a, b);
}

// smem layout (bytes)
#define OFF_CBP   0         // 133120
#define OFF_RES0  133120    //  33792
#define OFF_RES1  166912    //  33792
#define OFF_REDV  200704    //   8192
#define OFF_REDI  208896    //   8192
#define OFF_CCS   217088    //   1024
#define OFF_RRS   218112    //    256
#define OFF_BEST  218368    //    256
#define SMEM_BYTES 218624

__global__ __launch_bounds__(NTHREADS, 1)
void rvq_kernel(const float* __restrict__ x,
                const float* __restrict__ codebooks,
                float* __restrict__ out, int mode)
{
    extern __shared__ char smem[];
    unsigned long long* cbp = (unsigned long long*)(smem + OFF_CBP);
    float* resb[2] = { (float*)(smem + OFF_RES0), (float*)(smem + OFF_RES1) };
    float* redv = (float*)(smem + OFF_REDV);
    int*   redi = (int*)(smem + OFF_REDI);
    float* cc_s = (float*)(smem + OFF_CCS);
    float* rrs  = (float*)(smem + OFF_RRS);
    int*   best = (int*)(smem + OFF_BEST);

    const int t    = threadIdx.x;
    const int w    = t >> 5;
    const int lane = t & 31;
    const int itemgrp = (lane & 7) | ((w & 1) << 3);   // items itemgrp + 16u, u<4
    const int cg      = (lane >> 3) | ((w >> 1) << 2); // pairs  cg + 32*v2,  v2<4
    const int bid  = blockIdx.x;
    const int gsz  = gridDim.x;

    // residual-tile prefetch: 2048 granules of 16B, gmem row 512B -> smem row RSP*4
    auto prefetch_tile = [&](const float* src, int tl, int buf) {
        const char* gb = (const char*)(src + (size_t)tl * (MT * DIM));
        uint32_t sb = s2u(resb[buf]);
        #pragma unroll
        for (int n = 0; n < 4; n++) {
            int g   = t + NTHREADS * n;       // 0..2047
            int row = g >> 5, col = g & 31;
            CPA16(sb + row * (RSP * 4) + col * 16, gb + g * 16);
        }
        CPCOMMIT();
    };

    for (int stage = 0; stage < NCB; stage++) {
        __syncthreads();   // prior stage fully done (cbp + res buffers free)

        // ---- async load packed codebook + cc for this stage ----
        {
            const char* gb = (const char*)&g_cbp[stage * CBPN];
            uint32_t sb = s2u(cbp);
            #pragma unroll
            for (int n = 0; n < 16; n++) {
                int g = t + NTHREADS * n;     // 0..8191
                CPA16(sb + g * 16, gb + g * 16);
            }
            if (t < 128) {
                int g = NTHREADS * 16 + t;    // 8192..8319
                CPA16(sb + g * 16, gb + g * 16);
            }
            if (t < 64) CPA16(s2u(cc_s) + t * 16, (const char*)&g_cc[stage * KCW] + t * 16);
            CPCOMMIT();
        }
        const float* src = (stage == 0) ? x : g_res;

        int tl0 = bid;
        if (tl0 < NTILES) prefetch_tile(src, tl0, 0);

        int it = 0;
        for (int tl = tl0; tl < NTILES; tl += gsz, it++) {
            int buf = it & 1;
            float* res = resb[buf];

            CPWAIT0();
            __syncthreads();   // tile data + cbp ready; prev residual updates done

            // ---- rr: 8 thr/item, 16-elem double chains + shfl tree ----
            {
                int item = t >> 3, part = t & 7;
                const float* rp = res + item * RSP + part * 16;
                double s = 0.0;
                #pragma unroll
                for (int k = 0; k < 16; k++) { double v = (double)rp[k]; s += v * v; }
                #pragma unroll
                for (int o = 1; o < 8; o <<= 1)
                    s += __shfl_xor_sync(0xffffffffu, s, o);
                if (part == 0) rrs[item] = (float)s;
            }

            // ---- prefetch next tile into other buffer ----
            int tln = tl + gsz;
            if (tln < NTILES) prefetch_tile(src, tln, buf ^ 1);

            // ---- dot tile: FMA2, each lane a sequential k-ascending chain ----
            unsigned long long acc[4][4];
            #pragma unroll
            for (int u = 0; u < 4; u++)
                #pragma unroll
                for (int v2 = 0; v2 < 4; v2++) acc[u][v2] = 0ULL;

            const float* rb = res + itemgrp * RSP;
            const unsigned long long* cb0 = cbp + cg * RS2;

            ulonglong2 Ac[4], Bc[4];
            auto LOADC = [&](ulonglong2* C, int h) {
                #pragma unroll
                for (int v2 = 0; v2 < 4; v2++)
                    C[v2] = *(const ulonglong2*)(cb0 + v2 * 32 * RS2 + 2 * h);
            };
            auto DOFMA = [&](const ulonglong2* C, int h) {
                unsigned long long r0[4], r1[4];
                #pragma unroll
                for (int u = 0; u < 4; u++) {
                    float2 f = *(const float2*)(rb + u * 16 * RSP + 2 * h);
                    r0[u] = dup2(f.x); r1[u] = dup2(f.y);
                }
                #pragma unroll
                for (int u = 0; u < 4; u++)
                    #pragma unroll
                    for (int v2 = 0; v2 < 4; v2++)
                        FMA2(acc[u][v2], r0[u], C[v2].x);   // k = 2h
                #pragma unroll
                for (int u = 0; u < 4; u++)
                    #pragma unroll
                    for (int v2 = 0; v2 < 4; v2++)
                        FMA2(acc[u][v2], r1[u], C[v2].y);   // k = 2h+1
            };

            LOADC(Ac, 0);
            #pragma unroll 1
            for (int h = 0; h < DIM / 2 - 2; h += 2) {
                LOADC(Bc, h + 1);
                DOFMA(Ac, h);
                LOADC(Ac, h + 2);
                DOFMA(Bc, h + 1);
            }
            LOADC(Bc, DIM / 2 - 1);
            DOFMA(Ac, DIM / 2 - 2);
            DOFMA(Bc, DIM / 2 - 1);

            __syncthreads();   // rrs visible; acc in regs

            // ---- argmin of d2 = fl(fl(rr - 2*dot) + cc), cw ascending ----
            #pragma unroll
            for (int u = 0; u < 4; u++) {
                int item = itemgrp + 16 * u;
                float rrv = rrs[item];
                float bv = 3.0e38f; int bi = KCW;
                #pragma unroll
                for (int v2 = 0; v2 < 4; v2++) {
                    float2 dp = *(float2*)&acc[u][v2];
                    int cw = 2 * (cg + 32 * v2);
                    float d2a = __fadd_rn(__fmaf_rn(-2.0f, dp.x, rrv), cc_s[cw]);
                    if (d2a < bv) { bv = d2a; bi = cw; }
                    float d2b = __fadd_rn(__fmaf_rn(-2.0f, dp.y, rrv), cc_s[cw + 1]);
                    if (d2b < bv) { bv = d2b; bi = cw + 1; }
                }
                redv[cg * MT + item] = bv;
                redi[cg * MT + item] = bi;
            }
            __syncthreads();

            // ---- lex-min reduce: 8 thr/item read 4 slots + shfl tree ----
            {
                int item = t >> 3, base = (t & 7) * 4;
                float bv = 3.0e38f; int bi = KCW;
                #pragma unroll
                for (int q = 0; q < 4; q++) {
                    float v  = redv[(base + q) * MT + item];
                    int   i2 = redi[(base + q) * MT + item];
                    if (v < bv || (v == bv && i2 < bi)) { bv = v; bi = i2; }
                }
                #pragma unroll
                for (int o = 1; o < 8; o <<= 1) {
                    float v  = __shfl_xor_sync(0xffffffffu, bv, o);
                    int   i2 = __shfl_xor_sync(0xffffffffu, bi, o);
                    if (v < bv || (v == bv && i2 < bi)) { bv = v; bi = i2; }
                }
                if ((t & 7) == 0) {
                    best[item] = bi;
                    int gi = tl * MT + item;
                    if (stage < 2) g_idx[stage * N_ITEMS + gi] = bi;
                    if (mode == 0)      out[(size_t)gi * 3 + stage] = (float)bi;
                    else if (mode == 2) ((int*)out)[(size_t)gi * 3 + stage] = bi;
                }
            }
            __syncthreads();   // best ready

            int item = t >> 3, j0 = (t & 7) * 16;
            if (stage < 2) {
                // ---- residual update -> g_res ----
                int bi = best[item];
                const unsigned long long* cpr = cbp + (bi >> 1) * RS2;
                int sel = bi & 1;
                float* gout = g_res + (size_t)tl * (MT * DIM) + item * DIM + j0;
                #pragma unroll
                for (int m = 0; m < 4; m++) {
                    float4 r = *(const float4*)(res + item * RSP + j0 + 4 * m);
                    float2 ca = *(const float2*)&cpr[j0 + 4 * m + 0];
                    float2 cb2 = *(const float2*)&cpr[j0 + 4 * m + 1];
                    float2 cc2 = *(const float2*)&cpr[j0 + 4 * m + 2];
                    float2 cd = *(const float2*)&cpr[j0 + 4 * m + 3];
                    float c0 = sel ? ca.y : ca.x;
                    float c1 = sel ? cb2.y : cb2.x;
                    float c2 = sel ? cc2.y : cc2.x;
                    float c3 = sel ? cd.y : cd.x;
                    float4 o;
                    o.x = __fsub_rn(r.x, c0); o.y = __fsub_rn(r.y, c1);
                    o.z = __fsub_rn(r.z, c2); o.w = __fsub_rn(r.w, c3);
                    *(float4*)(gout + 4 * m) = o;
                }
            } else if (mode != 2) {
                // ---- quantized = fl(fl(c0 + c1) + c2), reference order ----
                int gi = tl * MT + item;
                int i0 = g_idx[gi];
                int i1 = g_idx[N_ITEMS + gi];
                int bi = best[item];
                const unsigned long long* cpr = cbp + (bi >> 1) * RS2;
                int sel = bi & 1;
                const float* r0 = codebooks + (size_t)i0 * DIM + j0;
                const float* r1 = codebooks + ((size_t)KCW + i1) * DIM + j0;
                float* outq = (mode == 0) ? (out + (size_t)N_ITEMS * 3) : out;
                float* gq = outq + (size_t)gi * DIM + j0;
                #pragma unroll
                for (int m = 0; m < 4; m++) {
                    float4 a = *(const float4*)(r0 + 4 * m);
                    float4 b = *(const float4*)(r1 + 4 * m);
                    float2 ca = *(const float2*)&cpr[j0 + 4 * m + 0];
                    float2 cb2 = *(const float2*)&cpr[j0 + 4 * m + 1];
                    float2 cc2 = *(const float2*)&cpr[j0 + 4 * m + 2];
                    float2 cd = *(const float2*)&cpr[j0 + 4 * m + 3];
                    float c0 = sel ? ca.y : ca.x;
                    float c1 = sel ? cb2.y : cb2.x;
                    float c2 = sel ? cc2.y : cc2.x;
                    float c3 = sel ? cd.y : cd.x;
                    float4 o;
                    o.x = __fadd_rn(__fadd_rn(a.x, b.x), c0);
                    o.y = __fadd_rn(__fadd_rn(a.y, b.y), c1);
                    o.z = __fadd_rn(__fadd_rn(a.z, b.z), c2);
                    o.w = __fadd_rn(__fadd_rn(a.w, b.w), c3);
                    *(float4*)(gq + 4 * m) = o;
                }
            }
        }
    }
}

extern "C" void kernel_launch(void* const* d_in, const int* in_sizes, int n_in,
                              void* d_out, int out_size)
{
    const float* x   = (const float*)d_in[0];
    const float* cbk = (const float*)d_in[1];
    if (n_in >= 2 && in_sizes[0] == NCB * KCW * DIM && in_sizes[1] == N_ITEMS * DIM) {
        const float* tmp = x; x = cbk; cbk = tmp;
    }

    int mode;
    if (out_size == N_ITEMS * (3 + DIM))      mode = 0;
    else if (out_size == N_ITEMS * DIM)       mode = 1;
    else if (out_size == N_ITEMS * 3)         mode = 2;
    else                                       mode = (out_size > N_ITEMS * DIM) ? 0 : 1;

    cc_kernel<<<NCB, KCW>>>(cbk);
    prepack_kernel<<<(NCB * 128 * DIM + 511) / 512, 512>>>(cbk);
    cudaFuncSetAttribute(rvq_kernel, cudaFuncAttributeMaxDynamicSharedMemorySize, SMEM_BYTES);
    rvq_kernel<<<GRID, NTHREADS, SMEM_BYTES>>>(x, cbk, (float*)d_out, mode);
}

// round 8
// speedup vs baseline: 1.0326x; 1.0020x over previous
#include <cuda_runtime.h>
#include <cstdint>

#define N_ITEMS  262144
#define DIM      128
#define NCB      3
#define KCW      256
#define MT       64
#define NTHREADS 512
#define GRID     152
#define NTILES   (N_ITEMS / MT)      // 4096
#define RSP      132                 // plain residual row stride (floats)
#define RS2      130                 // packed codebook row stride (ulonglong)
#define CBPN     (128 * RS2)         // 16640 ull per stage

#define FMA2(d, a, b) asm("fma.rn.f32x2 %0, %1, %2, %0;" : "+l"(d) : "l"(a), "l"(b))

__device__ __forceinline__ unsigned long long dup2(float f) {
    unsigned long long d; unsigned u = __float_as_uint(f);
    asm("mov.b64 %0, {%1, %1};" : "=l"(d) : "r"(u));
    return d;
}
__device__ __forceinline__ uint32_t s2u(const void* p) {
    return (uint32_t)__cvta_generic_to_shared(p);
}
#define CPA16(saddr, gptr) asm volatile("cp.async.ca.shared.global [%0], [%1], 16;" :: "r"(saddr), "l"(gptr))
#define CPCOMMIT()         asm volatile("cp.async.commit_group;")
#define CPWAIT0()          asm volatile("cp.async.wait_group 0;" ::: "memory")

__device__ float              g_cc[NCB * KCW];
__device__ unsigned long long g_cbp[NCB * CBPN];
__device__ float              g_res[(size_t)N_ITEMS * DIM];
__device__ int                g_idx[2 * N_ITEMS];

// ---- ||c||^2 in double (sequential k chain, as validated in R3-R6) ----
__global__ void cc_kernel(const float* __restrict__ codebooks) {
    int stage = blockIdx.x, j = threadIdx.x;
    const float* row = codebooks + ((size_t)stage * KCW + j) * DIM;
    double s = 0.0;
    #pragma unroll 8
    for (int k = 0; k < DIM; k++) { double v = (double)row[k]; s += v * v; }
    g_cc[stage * KCW + j] = (float)s;
}

// ---- prepack codebooks: g_cbp[s][p*RS2+k] = (c_{2p}[k], c_{2p+1}[k]) ----
__global__ void prepack_kernel(const float* __restrict__ codebooks) {
    int idx = blockIdx.x * blockDim.x + threadIdx.x;   // 0..49151
    if (idx >= NCB * 128 * DIM) return;
    int s = idx / (128 * DIM);
    int r = idx % (128 * DIM);
    int p = r / DIM, k = r % DIM;
    float a = codebooks[((size_t)s * KCW + 2 * p)     * DIM + k];
    float b = codebooks[((size_t)s * KCW + 2 * p + 1) * DIM + k];
    *(float2*)&g_cbp[s * CBPN + p * RS2 + k] = make_float2(a, b);
}

// smem layout (bytes)
#define OFF_CBP   0         // 133120
#define OFF_RES0  133120    //  33792
#define OFF_RES1  166912    //  33792
#define OFF_REDV  200704    //   8192
#define OFF_REDI  208896    //   8192
#define OFF_CCS   217088    //   1024
#define OFF_RRS   218112    //    256
#define OFF_BEST  218368    //    256
#define SMEM_BYTES 218624

__global__ __launch_bounds__(NTHREADS, 1)
void rvq_kernel(const float* __restrict__ x,
                const float* __restrict__ codebooks,
                float* __restrict__ out, int mode)
{
    extern __shared__ char smem[];
    unsigned long long* cbp = (unsigned long long*)(smem + OFF_CBP);
    float* resb[2] = { (float*)(smem + OFF_RES0), (float*)(smem + OFF_RES1) };
    float* redv = (float*)(smem + OFF_REDV);
    int*   redi = (int*)(smem + OFF_REDI);
    float* cc_s = (float*)(smem + OFF_CCS);
    float* rrs  = (float*)(smem + OFF_RRS);
    int*   best = (int*)(smem + OFF_BEST);

    const int t    = threadIdx.x;
    const int w    = t >> 5;
    const int lane = t & 31;
    const int itemgrp = (lane & 7) | ((w & 1) << 3);   // items itemgrp + 16u, u<4
    const int cg      = (lane >> 3) | ((w >> 1) << 2); // pairs  cg + 32*v2,  v2<4
    const int bid  = blockIdx.x;
    const int gsz  = gridDim.x;

    // residual-tile prefetch: 2048 granules of 16B, gmem row 512B -> smem row RSP*4
    auto prefetch_tile = [&](const float* src, int tl, int buf) {
        const char* gb = (const char*)(src + (size_t)tl * (MT * DIM));
        uint32_t sb = s2u(resb[buf]);
        #pragma unroll
        for (int n = 0; n < 4; n++) {
            int g   = t + NTHREADS * n;       // 0..2047
            int row = g >> 5, col = g & 31;
            CPA16(sb + row * (RSP * 4) + col * 16, gb + g * 16);
        }
        CPCOMMIT();
    };

    for (int stage = 0; stage < NCB; stage++) {
        __syncthreads();   // prior stage fully done (cbp + res buffers free)

        // ---- async load packed codebook + cc for this stage ----
        {
            const char* gb = (const char*)&g_cbp[stage * CBPN];
            uint32_t sb = s2u(cbp);
            #pragma unroll
            for (int n = 0; n < 16; n++) {
                int g = t + NTHREADS * n;     // 0..8191
                CPA16(sb + g * 16, gb + g * 16);
            }
            if (t < 128) {
                int g = NTHREADS * 16 + t;    // 8192..8319
                CPA16(sb + g * 16, gb + g * 16);
            }
            if (t < 64) CPA16(s2u(cc_s) + t * 16, (const char*)&g_cc[stage * KCW] + t * 16);
            CPCOMMIT();
        }
        const float* src = (stage == 0) ? x : g_res;

        int tl0 = bid;
        if (tl0 < NTILES) prefetch_tile(src, tl0, 0);

        int it = 0;
        for (int tl = tl0; tl < NTILES; tl += gsz, it++) {
            int buf = it & 1;
            float* res = resb[buf];

            CPWAIT0();
            __syncthreads();   // tile data + cbp ready; prev residual updates done

            // ---- rr: 8 thr/item, 16-elem double chains + shfl tree ----
            {
                int item = t >> 3, part = t & 7;
                const float* rp = res + item * RSP + part * 16;
                double s = 0.0;
                #pragma unroll
                for (int k = 0; k < 16; k++) { double v = (double)rp[k]; s += v * v; }
                #pragma unroll
                for (int o = 1; o < 8; o <<= 1)
                    s += __shfl_xor_sync(0xffffffffu, s, o);
                if (part == 0) rrs[item] = (float)s;
            }

            // ---- prefetch next tile into other buffer ----
            int tln = tl + gsz;
            if (tln < NTILES) prefetch_tile(src, tln, buf ^ 1);

            // ---- dot tile: FMA2, each lane a sequential k-ascending chain ----
            unsigned long long acc[4][4];
            #pragma unroll
            for (int u = 0; u < 4; u++)
                #pragma unroll
                for (int v2 = 0; v2 < 4; v2++) acc[u][v2] = 0ULL;

            const float* rb = res + itemgrp * RSP;
            const unsigned long long* cb0 = cbp + cg * RS2;

            ulonglong2 Ac[4], Bc[4];
            auto LOADC = [&](ulonglong2* C, int h) {
                #pragma unroll
                for (int v2 = 0; v2 < 4; v2++)
                    C[v2] = *(const ulonglong2*)(cb0 + v2 * 32 * RS2 + 2 * h);
            };
            auto DOFMA = [&](const ulonglong2* C, int h) {
                unsigned long long r0[4], r1[4];
                #pragma unroll
                for (int u = 0; u < 4; u++) {
                    float2 f = *(const float2*)(rb + u * 16 * RSP + 2 * h);
                    r0[u] = dup2(f.x); r1[u] = dup2(f.y);
                }
                #pragma unroll
                for (int u = 0; u < 4; u++)
                    #pragma unroll
                    for (int v2 = 0; v2 < 4; v2++)
                        FMA2(acc[u][v2], r0[u], C[v2].x);   // k = 2h
                #pragma unroll
                for (int u = 0; u < 4; u++)
                    #pragma unroll
                    for (int v2 = 0; v2 < 4; v2++)
                        FMA2(acc[u][v2], r1[u], C[v2].y);   // k = 2h+1
            };

            LOADC(Ac, 0);
            #pragma unroll 1
            for (int h = 0; h < DIM / 2 - 2; h += 2) {
                LOADC(Bc, h + 1);
                DOFMA(Ac, h);
                LOADC(Ac, h + 2);
                DOFMA(Bc, h + 1);
            }
            LOADC(Bc, DIM / 2 - 1);
            DOFMA(Ac, DIM / 2 - 2);
            DOFMA(Bc, DIM / 2 - 1);

            __syncthreads();   // rrs visible; acc in regs

            // ---- argmin of d2 = fl(fl(rr - 2*dot) + cc), cw ascending ----
            #pragma unroll
            for (int u = 0; u < 4; u++) {
                int item = itemgrp + 16 * u;
                float rrv = rrs[item];
                float bv = 3.0e38f; int bi = KCW;
                #pragma unroll
                for (int v2 = 0; v2 < 4; v2++) {
                    float2 dp = *(float2*)&acc[u][v2];
                    int cw = 2 * (cg + 32 * v2);
                    float d2a = __fadd_rn(__fmaf_rn(-2.0f, dp.x, rrv), cc_s[cw]);
                    if (d2a < bv) { bv = d2a; bi = cw; }
                    float d2b = __fadd_rn(__fmaf_rn(-2.0f, dp.y, rrv), cc_s[cw + 1]);
                    if (d2b < bv) { bv = d2b; bi = cw + 1; }
                }
                redv[cg * MT + item] = bv;
                redi[cg * MT + item] = bi;
            }
            __syncthreads();

            // ---- lex-min reduce: 8 thr/item read 4 slots + shfl tree ----
            {
                int item = t >> 3, base = (t & 7) * 4;
                float bv = 3.0e38f; int bi = KCW;
                #pragma unroll
                for (int q = 0; q < 4; q++) {
                    float v  = redv[(base + q) * MT + item];
                    int   i2 = redi[(base + q) * MT + item];
                    if (v < bv || (v == bv && i2 < bi)) { bv = v; bi = i2; }
                }
                #pragma unroll
                for (int o = 1; o < 8; o <<= 1) {
                    float v  = __shfl_xor_sync(0xffffffffu, bv, o);
                    int   i2 = __shfl_xor_sync(0xffffffffu, bi, o);
                    if (v < bv || (v == bv && i2 < bi)) { bv = v; bi = i2; }
                }
                if ((t & 7) == 0) {
                    best[item] = bi;
                    int gi = tl * MT + item;
                    if (stage < 2) g_idx[stage * N_ITEMS + gi] = bi;
                    if (mode == 0)      out[(size_t)gi * 3 + stage] = (float)bi;
                    else if (mode == 2) ((int*)out)[(size_t)gi * 3 + stage] = bi;
                }
            }
            __syncthreads();   // best ready

            int item = t >> 3, j0 = (t & 7) * 16;
            if (stage < 2) {
                // ---- residual update -> g_res ----
                int bi = best[item];
                const unsigned long long* cpr = cbp + (bi >> 1) * RS2;
                int sel = bi & 1;
                float* gout = g_res + (size_t)tl * (MT * DIM) + item * DIM + j0;
                #pragma unroll
                for (int m = 0; m < 4; m++) {
                    float4 r = *(const float4*)(res + item * RSP + j0 + 4 * m);
                    float2 ca = *(const float2*)&cpr[j0 + 4 * m + 0];
                    float2 cb2 = *(const float2*)&cpr[j0 + 4 * m + 1];
                    float2 cc2 = *(const float2*)&cpr[j0 + 4 * m + 2];
                    float2 cd = *(const float2*)&cpr[j0 + 4 * m + 3];
                    float c0 = sel ? ca.y : ca.x;
                    float c1 = sel ? cb2.y : cb2.x;
                    float c2 = sel ? cc2.y : cc2.x;
                    float c3 = sel ? cd.y : cd.x;
                    float4 o;
                    o.x = __fsub_rn(r.x, c0); o.y = __fsub_rn(r.y, c1);
                    o.z = __fsub_rn(r.z, c2); o.w = __fsub_rn(r.w, c3);
                    *(float4*)(gout + 4 * m) = o;
                }
            } else if (mode != 2) {
                // ---- quantized = fl(fl(c0 + c1) + c2), reference order ----
                int gi = tl * MT + item;
                int i0 = g_idx[gi];
                int i1 = g_idx[N_ITEMS + gi];
                int bi = best[item];
                const unsigned long long* cpr = cbp + (bi >> 1) * RS2;
                int sel = bi & 1;
                const float* r0 = codebooks + (size_t)i0 * DIM + j0;
                const float* r1 = codebooks + ((size_t)KCW + i1) * DIM + j0;
                float* outq = (mode == 0) ? (out + (size_t)N_ITEMS * 3) : out;
                float* gq = outq + (size_t)gi * DIM + j0;
                #pragma unroll
                for (int m = 0; m < 4; m++) {
                    float4 a = *(const float4*)(r0 + 4 * m);
                    float4 b = *(const float4*)(r1 + 4 * m);
                    float2 ca = *(const float2*)&cpr[j0 + 4 * m + 0];
                    float2 cb2 = *(const float2*)&cpr[j0 + 4 * m + 1];
                    float2 cc2 = *(const float2*)&cpr[j0 + 4 * m + 2];
                    float2 cd = *(const float2*)&cpr[j0 + 4 * m + 3];
                    float c0 = sel ? ca.y : ca.x;
                    float c1 = sel ? cb2.y : cb2.x;
                    float c2 = sel ? cc2.y : cc2.x;
                    float c3 = sel ? cd.y : cd.x;
                    float4 o;
                    o.x = __fadd_rn(__fadd_rn(a.x, b.x), c0);
                    o.y = __fadd_rn(__fadd_rn(a.y, b.y), c1);
                    o.z = __fadd_rn(__fadd_rn(a.z, b.z), c2);
                    o.w = __fadd_rn(__fadd_rn(a.w, b.w), c3);
                    *(float4*)(gq + 4 * m) = o;
                }
            }
        }
    }
}

extern "C" void kernel_launch(void* const* d_in, const int* in_sizes, int n_in,
                              void* d_out, int out_size)
{
    const float* x   = (const float*)d_in[0];
    const float* cbk = (const float*)d_in[1];
    if (n_in >= 2 && in_sizes[0] == NCB * KCW * DIM && in_sizes[1] == N_ITEMS * DIM) {
        const float* tmp = x; x = cbk; cbk = tmp;
    }

    int mode;
    if (out_size == N_ITEMS * (3 + DIM))      mode = 0;
    else if (out_size == N_ITEMS * DIM)       mode = 1;
    else if (out_size == N_ITEMS * 3)         mode = 2;
    else                                       mode = (out_size > N_ITEMS * DIM) ? 0 : 1;

    cc_kernel<<<NCB, KCW>>>(cbk);
    prepack_kernel<<<(NCB * 128 * DIM + 511) / 512, 512>>>(cbk);
    cudaFuncSetAttribute(rvq_kernel, cudaFuncAttributeMaxDynamicSharedMemorySize, SMEM_BYTES);
    rvq_kernel<<<GRID, NTHREADS, SMEM_BYTES>>>(x, cbk, (float*)d_out, mode);
}

// round 10
// speedup vs baseline: 1.3028x; 1.2616x over previous
#include <cuda_runtime.h>
#include <cuda_bf16.h>
#include <cstdint>

#define N_ITEMS  262144
#define DIM      128
#define NCB      3
#define KCW      256
#define TM       64
#define NTILES   (N_ITEMS / TM)   // 4096
#define NTHREADS 256
#define GRID     148
#define MARGIN   1.0e-2f
#define CAP      8
#define STB      528              // smem row stride bytes (264 bf16)

__device__ float g_cc[NCB * KCW];
__device__ float g_res[(size_t)N_ITEMS * DIM];
__device__ int   g_idx[2 * N_ITEMS];

__device__ __forceinline__ uint32_t s2u(const void* p) {
    return (uint32_t)__cvta_generic_to_shared(p);
}
#define LDSM4(r0,r1,r2,r3,a) asm volatile("ldmatrix.sync.aligned.m8n8.x4.shared.b16 {%0,%1,%2,%3}, [%4];" : "=r"(r0),"=r"(r1),"=r"(r2),"=r"(r3) : "r"(a))
#define LDSM2(r0,r1,a)       asm volatile("ldmatrix.sync.aligned.m8n8.x2.shared.b16 {%0,%1}, [%2];" : "=r"(r0),"=r"(r1) : "r"(a))
#define MMA16816(d,a0,a1,a2,a3,b0,b1) asm volatile( \
    "mma.sync.aligned.m16n8k16.row.col.f32.bf16.bf16.f32 " \
    "{%0,%1,%2,%3}, {%4,%5,%6,%7}, {%8,%9}, {%0,%1,%2,%3};" \
    : "+f"((d)[0]),"+f"((d)[1]),"+f"((d)[2]),"+f"((d)[3]) \
    : "r"(a0),"r"(a1),"r"(a2),"r"(a3),"r"(b0),"r"(b1))

// ---- ||c||^2 double sequential chain (validated association) ----
__global__ void cc_kernel(const float* __restrict__ codebooks) {
    int row = blockIdx.x * 32 + threadIdx.x;
    if (row >= NCB * KCW) return;
    const float* r = codebooks + (size_t)row * DIM;
    double s = 0.0;
    #pragma unroll 8
    for (int k = 0; k < DIM; k++) { double v = (double)r[k]; s += v * v; }
    g_cc[row] = (float)s;
}

// ---- exact d2: sequential k-ascending fmaf chain (validated R3-R7) ----
__device__ __noinline__ float exact_d2(const float* __restrict__ r,
                                       const float* __restrict__ c,
                                       float rr, float ccj) {
    float dot = 0.f;
    #pragma unroll
    for (int m = 0; m < 32; m++) {
        float4 a = ((const float4*)r)[m];
        float4 b = ((const float4*)c)[m];
        dot = __fmaf_rn(a.x, b.x, dot);
        dot = __fmaf_rn(a.y, b.y, dot);
        dot = __fmaf_rn(a.z, b.z, dot);
        dot = __fmaf_rn(a.w, b.w, dot);
    }
    return __fadd_rn(__fmaf_rn(-2.f, dot, rr), ccj);
}

__device__ __forceinline__ void split2(float v0, float v1, uint32_t& hi, uint32_t& mi) {
    __nv_bfloat16 h0 = __float2bfloat16(v0), h1 = __float2bfloat16(v1);
    float r0 = v0 - __bfloat162float(h0), r1 = v1 - __bfloat162float(h1);
    __nv_bfloat16 m0 = __float2bfloat16(r0), m1 = __float2bfloat16(r1);
    hi = (uint32_t)__bfloat16_as_ushort(h0) | ((uint32_t)__bfloat16_as_ushort(h1) << 16);
    mi = (uint32_t)__bfloat16_as_ushort(m0) | ((uint32_t)__bfloat16_as_ushort(m1) << 16);
}

// smem offsets (bytes, from 1024-aligned base)
#define O_A     0                     // 64*528  = 33792
#define O_B     33792                 // 256*528 = 135168
#define O_CC    168960                // 1024
#define O_RRS   169984                // 256
#define O_HM    170240                // 2*64*4 = 512
#define O_CNT   170752                // 256
#define O_CAND  171008                // 64*CAP*4 = 2048
#define O_BEST  173056                // 256
#define SMEM_BYTES (173312 + 1024)

__global__ __launch_bounds__(NTHREADS, 1)
void rvq_kernel(const float* __restrict__ x,
                const float* __restrict__ codebooks,
                float* __restrict__ out, int mode)
{
    extern __shared__ char smraw[];
    char* smem = (char*)(((uintptr_t)smraw + 1023) & ~(uintptr_t)1023);
    float* cc_s = (float*)(smem + O_CC);
    float* rrs  = (float*)(smem + O_RRS);
    float* hm   = (float*)(smem + O_HM);      // [2][64]
    int*   cnt  = (int*)(smem + O_CNT);
    int*   cand = (int*)(smem + O_CAND);      // [64][CAP]
    int*   best = (int*)(smem + O_BEST);

    const int t = threadIdx.x, w = t >> 5, lane = t & 31;
    const uint32_t sA = s2u(smem + O_A), sB = s2u(smem + O_B);
    const int mrow0 = 16 * (w & 3);           // warp's 16-item block
    const int colbase = 128 * (w >> 2);       // warp's 128-cw half

    for (int stage = 0; stage < NCB; stage++) {
        __syncthreads();
        // ---- B conversion: thread t = codeword row t ----
        {
            const float4* cr = (const float4*)(codebooks + ((size_t)stage * KCW + t) * DIM);
            char* hrow = smem + O_B + t * STB;
            #pragma unroll
            for (int m = 0; m < 32; m++) {
                float4 v = cr[m];
                uint32_t h0, mi0, h1, mi1;
                split2(v.x, v.y, h0, mi0);
                split2(v.z, v.w, h1, mi1);
                *(uint2*)(hrow + m * 8)       = make_uint2(h0, h1);
                *(uint2*)(hrow + 256 + m * 8) = make_uint2(mi0, mi1);
            }
            cc_s[t] = g_cc[stage * KCW + t];
        }
        const float* src = (stage == 0) ? x : g_res;
        __syncthreads();

        for (int tl = blockIdx.x; tl < NTILES; tl += GRID) {
            // ---- phase 1: A conversion + rr + zero cnt ----
            {
                int i = t >> 2, q = t & 3;
                const float4* rg = (const float4*)(src + (size_t)(tl * TM + i) * DIM + q * 32);
                char* arow = smem + O_A + i * STB + q * 64;
                double s = 0.0;
                #pragma unroll
                for (int m = 0; m < 8; m++) {
                    float4 v = rg[m];
                    double a = v.x, b = v.y, c = v.z, d = v.w;
                    s += a * a; s += b * b; s += c * c; s += d * d;
                    uint32_t h0, mi0, h1, mi1;
                    split2(v.x, v.y, h0, mi0);
                    split2(v.z, v.w, h1, mi1);
                    *(uint2*)(arow + m * 8)       = make_uint2(h0, h1);
                    *(uint2*)(arow + 256 + m * 8) = make_uint2(mi0, mi1);
                }
                s += __shfl_xor_sync(0xffffffffu, s, 1);
                s += __shfl_xor_sync(0xffffffffu, s, 2);
                if (q == 0) rrs[i] = (float)s;
                if (t < TM) cnt[t] = 0;
            }
            __syncthreads();

            // ---- phase 2: MMA, 3 passes (hh, hm, mh) x 8 k16-steps ----
            float d[16][4];
            #pragma unroll
            for (int nt = 0; nt < 16; nt++)
                #pragma unroll
                for (int e = 0; e < 4; e++) d[nt][e] = 0.f;

            const uint32_t aAddr0 = sA + (mrow0 + (lane & 15)) * STB + (lane >> 4) * 16;
            const uint32_t bAddr0 = sB + (colbase + (lane & 7)) * STB + ((lane >> 3) & 1) * 16;
            const int KA[3] = {0, 0, 256};   // byte offsets: mid region at +256
            const int KB[3] = {0, 256, 0};

            #pragma unroll 1
            for (int p = 0; p < 3; p++) {
                uint32_t aBase = aAddr0 + KA[p];
                uint32_t bBase = bAddr0 + KB[p];
                #pragma unroll 1
                for (int ks = 0; ks < 8; ks++) {
                    uint32_t a0, a1, a2, a3;
                    LDSM4(a0, a1, a2, a3, aBase + ks * 32);
                    #pragma unroll
                    for (int nt = 0; nt < 16; nt++) {
                        uint32_t b0, b1;
                        LDSM2(b0, b1, bBase + nt * 8 * STB + ks * 32);
                        MMA16816(d[nt], a0, a1, a2, a3, b0, b1);
                    }
                }
            }

            // ---- phase 3: approx d2 + per-item half-min ----
            const int item0 = mrow0 + (lane >> 2);
            const int item1 = item0 + 8;
            const float rr0 = rrs[item0], rr1 = rrs[item1];
            float mn0 = 3.0e38f, mn1 = 3.0e38f;
            #pragma unroll
            for (int nt = 0; nt < 16; nt++) {
                int n = colbase + nt * 8 + 2 * (lane & 3);
                float c0 = cc_s[n], c1 = cc_s[n + 1];
                d[nt][0] = __fadd_rn(__fmaf_rn(-2.f, d[nt][0], rr0), c0);
                d[nt][1] = __fadd_rn(__fmaf_rn(-2.f, d[nt][1], rr0), c1);
                d[nt][2] = __fadd_rn(__fmaf_rn(-2.f, d[nt][2], rr1), c0);
                d[nt][3] = __fadd_rn(__fmaf_rn(-2.f, d[nt][3], rr1), c1);
                mn0 = fminf(mn0, fminf(d[nt][0], d[nt][1]));
                mn1 = fminf(mn1, fminf(d[nt][2], d[nt][3]));
            }
            mn0 = fminf(mn0, __shfl_xor_sync(0xffffffffu, mn0, 1));
            mn0 = fminf(mn0, __shfl_xor_sync(0xffffffffu, mn0, 2));
            mn1 = fminf(mn1, __shfl_xor_sync(0xffffffffu, mn1, 1));
            mn1 = fminf(mn1, __shfl_xor_sync(0xffffffffu, mn1, 2));
            if ((lane & 3) == 0) {
                hm[(w >> 2) * TM + item0] = mn0;
                hm[(w >> 2) * TM + item1] = mn1;
            }
            __syncthreads();

            // ---- phase 4: candidate collection ----
            {
                float thr0 = fminf(hm[item0], hm[TM + item0]) + MARGIN;
                float thr1 = fminf(hm[item1], hm[TM + item1]) + MARGIN;
                #pragma unroll
                for (int nt = 0; nt < 16; nt++) {
                    int n = colbase + nt * 8 + 2 * (lane & 3);
                    #pragma unroll
                    for (int e = 0; e < 4; e++) {
                        int it = (e < 2) ? item0 : item1;
                        float thr = (e < 2) ? thr0 : thr1;
                        if (d[nt][e] <= thr) {
                            int slot = atomicAdd(&cnt[it], 1);
                            if (slot < CAP) cand[it * CAP + slot] = n + (e & 1);
                        }
                    }
                }
            }
            __syncthreads();

            // ---- phase 5: rescue + decide (t < 64) ----
            if (t < TM) {
                int c = cnt[t], bi;
                if (c == 1) {
                    bi = cand[t * CAP];
                } else {
                    const float* rrow = src + (size_t)(tl * TM + t) * DIM;
                    const float* cb0  = codebooks + (size_t)stage * KCW * DIM;
                    float rr = rrs[t];
                    float bv = 3.0e38f; bi = KCW;
                    if (c <= CAP) {
                        #pragma unroll 1
                        for (int q = 0; q < c; q++) {
                            int j = cand[t * CAP + q];
                            float e = exact_d2(rrow, cb0 + (size_t)j * DIM, rr, cc_s[j]);
                            if (e < bv || (e == bv && j < bi)) { bv = e; bi = j; }
                        }
                    } else {
                        #pragma unroll 1
                        for (int j = 0; j < KCW; j++) {
                            float e = exact_d2(rrow, cb0 + (size_t)j * DIM, rr, cc_s[j]);
                            if (e < bv || (e == bv && j < bi)) { bv = e; bi = j; }
                        }
                    }
                }
                best[t] = bi;
                int gi = tl * TM + t;
                if (stage < 2) g_idx[stage * N_ITEMS + gi] = bi;
                if (mode == 0)      out[(size_t)gi * 3 + stage] = (float)bi;
                else if (mode == 2) ((int*)out)[(size_t)gi * 3 + stage] = bi;
            }
            __syncthreads();

            // ---- phase 6: residual update / quantize (gmem only) ----
            {
                int i = t >> 2, off = (t & 3) * 32;
                int gi = tl * TM + i;
                if (stage < 2) {
                    int bi = best[i];
                    const float4* cr = (const float4*)(codebooks + ((size_t)stage * KCW + bi) * DIM + off);
                    const float4* rg = (const float4*)(src + (size_t)gi * DIM + off);
                    float4* go = (float4*)(g_res + (size_t)gi * DIM + off);
                    #pragma unroll
                    for (int m = 0; m < 8; m++) {
                        float4 r = rg[m], c = cr[m], o;
                        o.x = __fsub_rn(r.x, c.x); o.y = __fsub_rn(r.y, c.y);
                        o.z = __fsub_rn(r.z, c.z); o.w = __fsub_rn(r.w, c.w);
                        go[m] = o;
                    }
                } else if (mode != 2) {
                    int i0 = g_idx[gi], i1 = g_idx[N_ITEMS + gi], i2 = best[i];
                    const float4* c0 = (const float4*)(codebooks + (size_t)i0 * DIM + off);
                    const float4* c1 = (const float4*)(codebooks + ((size_t)KCW + i1) * DIM + off);
                    const float4* c2 = (const float4*)(codebooks + ((size_t)2 * KCW + i2) * DIM + off);
                    float* outq = (mode == 0) ? (out + (size_t)N_ITEMS * 3) : out;
                    float4* go = (float4*)(outq + (size_t)gi * DIM + off);
                    #pragma unroll
                    for (int m = 0; m < 8; m++) {
                        float4 a = c0[m], b = c1[m], c = c2[m], o;
                        o.x = __fadd_rn(__fadd_rn(a.x, b.x), c.x);
                        o.y = __fadd_rn(__fadd_rn(a.y, b.y), c.y);
                        o.z = __fadd_rn(__fadd_rn(a.z, b.z), c.z);
                        o.w = __fadd_rn(__fadd_rn(a.w, b.w), c.w);
                        go[m] = o;
                    }
                }
            }
        }
    }
}

extern "C" void kernel_launch(void* const* d_in, const int* in_sizes, int n_in,
                              void* d_out, int out_size)
{
    const float* x   = (const float*)d_in[0];
    const float* cbk = (const float*)d_in[1];
    if (n_in >= 2 && in_sizes[0] == NCB * KCW * DIM && in_sizes[1] == N_ITEMS * DIM) {
        const float* tmp = x; x = cbk; cbk = tmp;
    }
    int mode;
    if (out_size == N_ITEMS * (3 + DIM))      mode = 0;
    else if (out_size == N_ITEMS * DIM)       mode = 1;
    else if (out_size == N_ITEMS * 3)         mode = 2;
    else                                       mode = (out_size > N_ITEMS * DIM) ? 0 : 1;

    cc_kernel<<<(NCB * KCW + 31) / 32, 32>>>(cbk);
    cudaFuncSetAttribute(rvq_kernel, cudaFuncAttributeMaxDynamicSharedMemorySize, SMEM_BYTES);
    rvq_kernel<<<GRID, NTHREADS, SMEM_BYTES>>>(x, cbk, (float*)d_out, mode);
}